// round 15
// baseline (speedup 1.0000x reference)
#include <cuda_runtime.h>
#include <cuda_bf16.h>
#include <math.h>
#include <stdint.h>

// Problem dims (fixed)
#define NT 2048
#define NB 64
#define NI 256
#define NH 512
#define NG 2048
#define GRID_B 128   // 32 unit-groups (16 units) x 4 batch-groups (16 batches)

// Scratch (__device__ globals; no allocation allowed)
__device__ float g_xw[(size_t)NT * NG * NB];     // [t][col][b]
__device__ float g_h[2 * NH * NB];               // [buf][b][k]  (k contiguous)
__device__ unsigned g_flag[4 * 32 * 32];         // flag[(bgp*32+slice)*32]: 8/step
__device__ uint4 g_xpack[(size_t)(NT * NB) * 64]; // x split-bf16, frag-packed
__device__ uint4 g_wpack[(size_t)NG * 64];        // Wi split-bf16, frag-packed

__device__ __forceinline__ float fast_sigmoid(float x) {
    return __fdividef(1.0f, 1.0f + __expf(-x));
}
__device__ __forceinline__ float fast_tanh(float x) {
    float t = __expf(2.0f * x);
    return 1.0f - __fdividef(2.0f, t + 1.0f);
}
__device__ __forceinline__ unsigned ld_acquire(const unsigned* p) {
    unsigned v;
    asm volatile("ld.acquire.gpu.global.b32 %0, [%1];" : "=r"(v) : "l"(p));
    return v;
}
__device__ __forceinline__ void cp16b(void* smem_dst, const void* gsrc) {
    unsigned d = (unsigned)__cvta_generic_to_shared(smem_dst);
    asm volatile("cp.async.ca.shared.global [%0], [%1], 16;" :: "r"(d), "l"(gsrc));
}

// pack (f_even, f_odd) -> u32 bf16x2, even in LOW half
__device__ __forceinline__ unsigned bfpk(float f_even, float f_odd) {
    unsigned r;
    asm("cvt.rn.bf16x2.f32 %0, %1, %2;" : "=r"(r) : "f"(f_odd), "f"(f_even));
    return r;
}
__device__ __forceinline__ float bflo(unsigned p) { return __uint_as_float(p << 16); }
__device__ __forceinline__ float bfhi(unsigned p) { return __uint_as_float(p & 0xFFFF0000u); }

__device__ __forceinline__ uint4 split4(float f0, float f1, float f2, float f3) {
    uint4 r;
    r.x = bfpk(f0, f1);
    r.y = bfpk(f2, f3);
    r.z = bfpk(f0 - bflo(r.x), f1 - bfhi(r.x));
    r.w = bfpk(f2 - bflo(r.y), f3 - bfhi(r.y));
    return r;
}

__device__ __forceinline__ void mma_bf16(float* d, unsigned a0, unsigned a1,
                                         unsigned a2, unsigned a3,
                                         unsigned b0, unsigned b1) {
    asm volatile(
        "mma.sync.aligned.m16n8k16.row.col.f32.bf16.bf16.f32 "
        "{%0,%1,%2,%3}, {%4,%5,%6,%7}, {%8,%9}, {%0,%1,%2,%3};"
        : "+f"(d[0]), "+f"(d[1]), "+f"(d[2]), "+f"(d[3])
        : "r"(a0), "r"(a1), "r"(a2), "r"(a3), "r"(b0), "r"(b1));
}

// ---------------- Phase 0: pack x and Wi into mma fragment layouts ----------------
__global__ void __launch_bounds__(256)
pack_kernel(const float* __restrict__ x, const float* __restrict__ Wi) {
    const int tid = threadIdx.x;
    size_t id = (size_t)blockIdx.x * 256 + tid;

    {   // x pack
        int m = (int)(id >> 6), e = (int)(id & 63);
        int k0 = ((e >> 2) << 4) + ((e & 3) << 1);
        const float* xr = x + (size_t)m * NI;
        float2 p0 = *reinterpret_cast<const float2*>(xr + k0);
        float2 p1 = *reinterpret_cast<const float2*>(xr + k0 + 8);
        g_xpack[id] = split4(p0.x, p0.y, p1.x, p1.y);
    }
    if (blockIdx.x < 512) {   // Wi pack
        int wi = blockIdx.x * 256 + tid;
        int e = wi >> 11, n = wi & 2047;
        int k0 = ((e >> 2) << 4) + ((e & 3) << 1);
        float b00 = Wi[(size_t)k0 * NG + n];
        float b01 = Wi[(size_t)(k0 + 1) * NG + n];
        float b10 = Wi[(size_t)(k0 + 8) * NG + n];
        float b11 = Wi[(size_t)(k0 + 9) * NG + n];
        g_wpack[(size_t)n * 64 + e] = split4(b00, b01, b10, b11);
    }
    if (blockIdx.x == 1000) {   // init h0 (buffer 0) + flags every launch/replay
        float4 z4 = make_float4(0.f, 0.f, 0.f, 0.f);
        #pragma unroll
        for (int i = 0; i < 32; i++)
            reinterpret_cast<float4*>(g_h)[tid + (i << 8)] = z4;
        if (tid < 128) g_flag[tid * 32] = 0u;
    }
}

// ---------------- Phase 1: xW via split-bf16 mma.sync (R12 exact) ----------------
#define PE 20
#define GEMM_SMEM (2 * 128 * PE * 16)   // 81920 B

__global__ void __launch_bounds__(256, 2)
xw_mma_kernel(const float* __restrict__ bias) {
    extern __shared__ uint4 smem4[];
    uint4* aS = smem4;
    uint4* bS = smem4 + 128 * PE;

    const int tid = threadIdx.x;
    const int wid = tid >> 5, lane = tid & 31;
    const int g = lane >> 2, t = lane & 3;
    const int wm = wid >> 1, wn = wid & 1;
    const int bn = blockIdx.x << 7, bm = blockIdx.y << 7;

    float d[2][8][4];
    #pragma unroll
    for (int mt = 0; mt < 2; mt++)
        #pragma unroll
        for (int nt = 0; nt < 8; nt++)
            #pragma unroll
            for (int i = 0; i < 4; i++) d[mt][nt][i] = 0.f;

    for (int c = 0; c < 4; c++) {
        #pragma unroll
        for (int j = tid; j < 2048; j += 256) {
            int row = j >> 4, el = j & 15;
            cp16b(aS + row * PE + el, &g_xpack[(size_t)(bm + row) * 64 + c * 16 + el]);
            cp16b(bS + row * PE + el, &g_wpack[(size_t)(bn + row) * 64 + c * 16 + el]);
        }
        asm volatile("cp.async.commit_group;");
        asm volatile("cp.async.wait_group 0;");
        __syncthreads();

        #pragma unroll
        for (int ks = 0; ks < 4; ks++) {
            uint4 a0r0 = aS[(wm * 32 + g) * PE + ks * 4 + t];
            uint4 a0r8 = aS[(wm * 32 + g + 8) * PE + ks * 4 + t];
            uint4 a1r0 = aS[(wm * 32 + 16 + g) * PE + ks * 4 + t];
            uint4 a1r8 = aS[(wm * 32 + 24 + g) * PE + ks * 4 + t];
            #pragma unroll
            for (int nt = 0; nt < 8; nt++) {
                uint4 b = bS[(wn * 64 + nt * 8 + g) * PE + ks * 4 + t];
                mma_bf16(d[0][nt], a0r0.x, a0r8.x, a0r0.y, a0r8.y, b.x, b.y);
                mma_bf16(d[0][nt], a0r0.x, a0r8.x, a0r0.y, a0r8.y, b.z, b.w);
                mma_bf16(d[0][nt], a0r0.z, a0r8.z, a0r0.w, a0r8.w, b.x, b.y);
                mma_bf16(d[1][nt], a1r0.x, a1r8.x, a1r0.y, a1r8.y, b.x, b.y);
                mma_bf16(d[1][nt], a1r0.x, a1r8.x, a1r0.y, a1r8.y, b.z, b.w);
                mma_bf16(d[1][nt], a1r0.z, a1r8.z, a1r0.w, a1r8.w, b.x, b.y);
            }
        }
        __syncthreads();
    }

    #pragma unroll
    for (int nt = 0; nt < 8; nt++) {
        int c0 = bn + wn * 64 + nt * 8 + 2 * t;
        float bb0 = bias[c0], bb1 = bias[c0 + 1];
        #pragma unroll
        for (int mt = 0; mt < 2; mt++) {
            int r0 = bm + wm * 32 + mt * 16 + g;
            int r1 = r0 + 8;
            size_t a0 = ((size_t)(r0 >> 6) * NG + c0) * NB + (r0 & 63);
            size_t a1 = ((size_t)(r1 >> 6) * NG + c0) * NB + (r1 & 63);
            g_xw[a0]      = d[mt][nt][0] + bb0;
            g_xw[a0 + NB] = d[mt][nt][1] + bb1;
            g_xw[a1]      = d[mt][nt][2] + bb0;
            g_xw[a1 + NB] = d[mt][nt][3] + bb1;
        }
    }
}

// ---------------- Phase 2: persistent recurrence on HMMA (split-bf16) ----------------
// CTA (ug, bgp): M=64 gate cols (m = gt*16 + u), N=16 batches, K=512.
// Warps 0-7: (mt=wid&3 -> gate, nt=wid>>2) own m16n8 tile, FULL K in registers
//   (3 accumulator chains: hi.hi, hi.lo, lo.hi) -> NO K-split reduce.
// Warps 8-15: cell (u=ct&15, b=ct>>4), publish via release-counting flags.
// All 16 warps stage h: per-lane flag wait, fragment-packed B entries.
// A fragments pre-packed once (AH/AL, 64KB each). BF padded rows (33 uint4).
#define SM_AH 0
#define SM_AL 65536
#define SM_BF 131072                        // uint4[2112]: nt stride 1056, s stride 33
#define SM_GATE (SM_BF + 2112 * 16)         // float[1024]
#define SMEM2_BYTES (SM_GATE + 4096)        // 168960

__global__ void __launch_bounds__(512, 1)
lstm_rec_kernel(const float* __restrict__ Wh, float* __restrict__ out, int write_state) {
    extern __shared__ char smem[];
    uint4* AH = reinterpret_cast<uint4*>(smem + SM_AH);   // [mt][s][t*8+g]
    uint4* AL = reinterpret_cast<uint4*>(smem + SM_AL);
    uint4* BF = reinterpret_cast<uint4*>(smem + SM_BF);   // [nt]{1056} [s]{33} [t*8+g]
    float* sGate = reinterpret_cast<float*>(smem + SM_GATE); // [gt][b16][u16]

    const int tid = threadIdx.x;
    const int wid = tid >> 5;
    const int lane = tid & 31;
    const int ug = blockIdx.x >> 2;
    const int bgp = blockIdx.x & 3;

    // One-time A (Wh) fragment pack: hi + lo entries.
    for (int e = tid; e < 4096; e += 512) {
        int mt = e >> 10, s = (e >> 5) & 31, i = e & 31;
        int t = i >> 3, g = i & 7;
        int colA = mt * NH + (ug << 4) + g;       // row m = mt*16+g
        int colB = colA + 8;                      // row m = mt*16+g+8
        int k0 = (s << 4) + (t << 1);
        float a00 = Wh[(size_t)k0 * NG + colA];
        float a01 = Wh[(size_t)(k0 + 1) * NG + colA];
        float a02 = Wh[(size_t)(k0 + 8) * NG + colA];
        float a03 = Wh[(size_t)(k0 + 9) * NG + colA];
        float b00 = Wh[(size_t)k0 * NG + colB];
        float b01 = Wh[(size_t)(k0 + 1) * NG + colB];
        float b02 = Wh[(size_t)(k0 + 8) * NG + colB];
        float b03 = Wh[(size_t)(k0 + 9) * NG + colB];
        uint4 hi, lo;
        hi.x = bfpk(a00, a01); hi.y = bfpk(b00, b01);
        hi.z = bfpk(a02, a03); hi.w = bfpk(b02, b03);
        lo.x = bfpk(a00 - bflo(hi.x), a01 - bfhi(hi.x));
        lo.y = bfpk(b00 - bflo(hi.y), b01 - bfhi(hi.y));
        lo.z = bfpk(a02 - bflo(hi.z), a03 - bfhi(hi.z));
        lo.w = bfpk(b02 - bflo(hi.w), b03 - bfhi(hi.w));
        AH[e] = hi;
        AL[e] = lo;
    }
    __syncthreads();

    // staging mapping: lane (bq, hf) -> batch bq, kstep s = 2*wid+hf
    const int bq = lane >> 1, hf = lane & 1;
    const int s_st = 2 * wid + hf;
    const int nt_st = bq >> 3, g_st = bq & 7;
    const unsigned* myfl = &g_flag[(bgp * 32 + s_st) * 32];

    // matmul mapping (wid<8)
    const int mt = wid & 3, ntm = wid >> 2;
    const int gm = lane >> 2, tm = lane & 3;
    const uint4* ahp = AH + mt * 1024 + tm * 8 + gm;
    const uint4* alp = AL + mt * 1024 + tm * 8 + gm;
    const uint4* bfp = BF + ntm * 1056 + tm * 8 + gm;

    // cell mapping (wid>=8)
    const int ct = tid - 256;
    const int u_ = ct & 15, b2 = ct >> 4;
    const int hrow = (ug << 4) + u_;
    const int bglob = (bgp << 4) + b2;
    unsigned* flown = &g_flag[(bgp * 32 + ug) * 32];
    float c_reg = 0.f;

    for (int t = 0; t < NT; t++) {
        const unsigned need = 8u * (unsigned)t;

        // xW prefetch (cell warps) — in flight through staging + matmul.
        float xw0 = 0.f, xw1 = 0.f, xw2 = 0.f, xw3 = 0.f;
        if (wid >= 8) {
            const float* xwt = g_xw + (size_t)t * ((size_t)NG * NB) + (size_t)hrow * NB + bglob;
            xw0 = __ldcs(xwt);
            xw1 = __ldcs(xwt + (size_t)(1 << 9) * NB);
            xw2 = __ldcs(xwt + (size_t)(2 << 9) * NB);
            xw3 = __ldcs(xwt + (size_t)(3 << 9) * NB);
        }

        // ---- stage own 16 k of batch bq: convert to fragment entries ----
        {
            while (ld_acquire(myfl) < need) { }
            const float* src = g_h + (t & 1) * (NH * NB)
                             + (size_t)((bgp << 4) + bq) * NH + (s_st << 4);
            float4 v0 = __ldcg(reinterpret_cast<const float4*>(src));
            float4 v1 = __ldcg(reinterpret_cast<const float4*>(src + 4));
            float4 v2 = __ldcg(reinterpret_cast<const float4*>(src + 8));
            float4 v3 = __ldcg(reinterpret_cast<const float4*>(src + 12));
            float a[16] = {v0.x, v0.y, v0.z, v0.w, v1.x, v1.y, v1.z, v1.w,
                           v2.x, v2.y, v2.z, v2.w, v3.x, v3.y, v3.z, v3.w};
            unsigned hw[8], lw[8];
            #pragma unroll
            for (int p = 0; p < 8; p++) {
                hw[p] = bfpk(a[2 * p], a[2 * p + 1]);
                lw[p] = bfpk(a[2 * p] - bflo(hw[p]), a[2 * p + 1] - bfhi(hw[p]));
            }
            uint4* e0 = BF + nt_st * 1056 + s_st * 33 + g_st;
            #pragma unroll
            for (int tt = 0; tt < 4; tt++)
                e0[tt * 8] = make_uint4(hw[tt], hw[tt + 4], lw[tt], lw[tt + 4]);
        }
        __syncthreads();   // all B fragments staged

        // ---- matmul warps: full-K HMMA, 3 accumulator chains ----
        if (wid < 8) {
            float dA[4] = {0.f, 0.f, 0.f, 0.f};
            float dB[4] = {0.f, 0.f, 0.f, 0.f};
            float dC[4] = {0.f, 0.f, 0.f, 0.f};
            #pragma unroll 8
            for (int s = 0; s < 32; s++) {
                uint4 H = ahp[s * 32];
                uint4 L = alp[s * 32];
                uint4 Bv = bfp[s * 33];
                mma_bf16(dA, H.x, H.y, H.z, H.w, Bv.x, Bv.y);   // hi.hi
                mma_bf16(dB, H.x, H.y, H.z, H.w, Bv.z, Bv.w);   // hi.lo
                mma_bf16(dC, L.x, L.y, L.z, L.w, Bv.x, Bv.y);   // lo.hi
            }
            const int b0 = (ntm << 3) + (tm << 1);
            float* sg = sGate + (mt << 8);
            sg[b0 * 16 + gm]           = dA[0] + dB[0] + dC[0];
            sg[(b0 + 1) * 16 + gm]     = dA[1] + dB[1] + dC[1];
            sg[b0 * 16 + gm + 8]       = dA[2] + dB[2] + dC[2];
            sg[(b0 + 1) * 16 + gm + 8] = dA[3] + dB[3] + dC[3];
        }
        __syncthreads();   // sGate ready

        // ---- cell warps ----
        if (wid >= 8) {
            const float* sg = sGate + (b2 << 4) + u_;
            float G0 = sg[0]   + xw0;
            float G1 = sg[256] + xw1;
            float G2 = sg[512] + xw2;
            float G3 = sg[768] + xw3;
            float ig = fast_sigmoid(G0);
            float fg = fast_sigmoid(G1);
            float gg = fast_tanh(G2);
            float og = fast_sigmoid(G3);
            c_reg = fg * c_reg + ig * gg;
            float h = og * fast_tanh(c_reg);

            __stcg(&g_h[((t + 1) & 1) * (NH * NB) + (size_t)bglob * NH + hrow], h);
            __syncwarp();   // warp's h-stores ordered before release
            if ((lane) == 0) {
                asm volatile("red.release.gpu.global.add.u32 [%0], %1;"
                             :: "l"(flown), "r"(1u) : "memory");
            }
            // Off the critical path:
            __stcs(&out[((size_t)t * NB + bglob) * NH + hrow], h);
            if (write_state && t == NT - 1) {
                size_t base = (size_t)NT * NB * NH;
                out[base + (size_t)bglob * NH + hrow] = h;
                out[base + (size_t)NB * NH + (size_t)bglob * NH + hrow] = c_reg;
            }
        }
        // No loop-end sync needed: BF restage (t+1) is gated by flags >= 8(t+1),
        // published only after this CTA's cell warps pass their reads; sGate
        // rewrite happens after sync#1 of t+1 which all warps must reach.
    }
}

extern "C" void kernel_launch(void* const* d_in, const int* in_sizes, int n_in,
                              void* d_out, int out_size) {
    const float* x  = (const float*)d_in[0];
    const float* Wi = (const float*)d_in[1];
    const float* Wh = (const float*)d_in[2];
    const float* B  = (const float*)d_in[3];
    float* out = (float*)d_out;

    cudaFuncSetAttribute(xw_mma_kernel, cudaFuncAttributeMaxDynamicSharedMemorySize,
                         GEMM_SMEM);
    cudaFuncSetAttribute(lstm_rec_kernel, cudaFuncAttributeMaxDynamicSharedMemorySize,
                         SMEM2_BYTES);

    // Phase 0: pack x + Wi; init h0/flags.
    pack_kernel<<<(NT * NB * 64) / 256, 256>>>(x, Wi);

    // Phase 1: tensor-core GEMM.
    dim3 gA(NG / 128, (NT * NB) / 128);
    xw_mma_kernel<<<gA, 256, GEMM_SMEM>>>(B);

    const long long need_full = (long long)NT * NB * NH + 2LL * NB * NH;
    int write_state = ((long long)out_size >= need_full) ? 1 : 0;

    // Phase 2: persistent recurrence on tensor cores.
    lstm_rec_kernel<<<GRID_B, 512, SMEM2_BYTES>>>(Wh, out, write_state);
}

// round 17
// speedup vs baseline: 1.5405x; 1.5405x over previous
#include <cuda_runtime.h>
#include <cuda_bf16.h>
#include <math.h>
#include <stdint.h>

// Problem dims (fixed)
#define NT 2048
#define NB 64
#define NI 256
#define NH 512
#define NG 2048
#define GRID_B 128   // 32 unit-groups x 4 batch-groups, 1 CTA/SM, single wave

// Scratch (__device__ globals; no allocation allowed)
__device__ float g_xw[(size_t)NT * NG * NB];     // [t][col][b]
__device__ float g_h[2 * NH * NB];               // [buf][k][b]
__device__ unsigned g_flag[4 * 32 * 32];         // flag[(bgp*32+ug)*32]: 8 per step
__device__ uint4 g_xpack[(size_t)(NT * NB) * 64]; // 134MB: x split-bf16, frag-packed
__device__ uint4 g_wpack[(size_t)NG * 64];        // 2MB: Wi split-bf16, frag-packed

__device__ __forceinline__ float fast_sigmoid(float x) {
    return __fdividef(1.0f, 1.0f + __expf(-x));
}
__device__ __forceinline__ float fast_tanh(float x) {
    float t = __expf(2.0f * x);
    return 1.0f - __fdividef(2.0f, t + 1.0f);
}
__device__ __forceinline__ unsigned ld_acquire(const unsigned* p) {
    unsigned v;
    asm volatile("ld.acquire.gpu.global.b32 %0, [%1];" : "=r"(v) : "l"(p));
    return v;
}
__device__ __forceinline__ void cp16b(void* smem_dst, const void* gsrc) {
    unsigned d = (unsigned)__cvta_generic_to_shared(smem_dst);
    asm volatile("cp.async.ca.shared.global [%0], [%1], 16;" :: "r"(d), "l"(gsrc));
}

// pack (f_even, f_odd) -> u32 bf16x2, even in LOW half
__device__ __forceinline__ unsigned bfpk(float f_even, float f_odd) {
    unsigned r;
    asm("cvt.rn.bf16x2.f32 %0, %1, %2;" : "=r"(r) : "f"(f_odd), "f"(f_even));
    return r;
}
__device__ __forceinline__ float bflo(unsigned p) { return __uint_as_float(p << 16); }
__device__ __forceinline__ float bfhi(unsigned p) { return __uint_as_float(p & 0xFFFF0000u); }

__device__ __forceinline__ uint4 split4(float f0, float f1, float f2, float f3) {
    uint4 r;
    r.x = bfpk(f0, f1);
    r.y = bfpk(f2, f3);
    r.z = bfpk(f0 - bflo(r.x), f1 - bfhi(r.x));
    r.w = bfpk(f2 - bflo(r.y), f3 - bfhi(r.y));
    return r;
}

__device__ __forceinline__ void mma_bf16(float* d, unsigned a0, unsigned a1,
                                         unsigned a2, unsigned a3,
                                         unsigned b0, unsigned b1) {
    asm volatile(
        "mma.sync.aligned.m16n8k16.row.col.f32.bf16.bf16.f32 "
        "{%0,%1,%2,%3}, {%4,%5,%6,%7}, {%8,%9}, {%0,%1,%2,%3};"
        : "+f"(d[0]), "+f"(d[1]), "+f"(d[2]), "+f"(d[3])
        : "r"(a0), "r"(a1), "r"(a2), "r"(a3), "r"(b0), "r"(b1));
}

// ---------------- Phase 0: pack x and Wi into mma fragment layouts ----------------
__global__ void __launch_bounds__(256)
pack_kernel(const float* __restrict__ x, const float* __restrict__ Wi) {
    const int tid = threadIdx.x;
    size_t id = (size_t)blockIdx.x * 256 + tid;

    {   // x pack
        int m = (int)(id >> 6), e = (int)(id & 63);
        int k0 = ((e >> 2) << 4) + ((e & 3) << 1);
        const float* xr = x + (size_t)m * NI;
        float2 p0 = *reinterpret_cast<const float2*>(xr + k0);
        float2 p1 = *reinterpret_cast<const float2*>(xr + k0 + 8);
        g_xpack[id] = split4(p0.x, p0.y, p1.x, p1.y);
    }
    if (blockIdx.x < 512) {   // Wi pack
        int wi = blockIdx.x * 256 + tid;
        int e = wi >> 11, n = wi & 2047;
        int k0 = ((e >> 2) << 4) + ((e & 3) << 1);
        float b00 = Wi[(size_t)k0 * NG + n];
        float b01 = Wi[(size_t)(k0 + 1) * NG + n];
        float b10 = Wi[(size_t)(k0 + 8) * NG + n];
        float b11 = Wi[(size_t)(k0 + 9) * NG + n];
        g_wpack[(size_t)n * 64 + e] = split4(b00, b01, b10, b11);
    }
    if (blockIdx.x == 1000) {   // init h0 (buffer 0) + flags every launch/replay
        float4 z4 = make_float4(0.f, 0.f, 0.f, 0.f);
        #pragma unroll
        for (int i = 0; i < 32; i++)
            reinterpret_cast<float4*>(g_h)[tid + (i << 8)] = z4;
        if (tid < 128) g_flag[tid * 32] = 0u;
    }
}

// ---------------- Phase 1: xW via split-bf16 mma.sync, K=32 chunks, db @ occ2 ----
// 8 chunks of 8 entries/row; pitch 12 (12 mod 8 = 4 -> phase-quads conflict-free).
// Stage = A+B chunk = 3072 uint4 = 48KB; 2 stages = 96KB -> occupancy 2.
#define PE2 12
#define STAGE_U4 (2 * 128 * PE2)
#define GEMM_SMEM (2 * STAGE_U4 * 16)   // 98304 B

__global__ void __launch_bounds__(256, 2)
xw_mma_kernel(const float* __restrict__ bias) {
    extern __shared__ uint4 smem4[];

    const int tid = threadIdx.x;
    const int wid = tid >> 5, lane = tid & 31;
    const int g = lane >> 2, t = lane & 3;
    const int wm = wid >> 1, wn = wid & 1;
    const int bn = blockIdx.x << 7, bm = blockIdx.y << 7;

    float d[2][8][4];
    #pragma unroll
    for (int mt = 0; mt < 2; mt++)
        #pragma unroll
        for (int nt = 0; nt < 8; nt++)
            #pragma unroll
            for (int i = 0; i < 4; i++) d[mt][nt][i] = 0.f;

    // 128 rows x 8 entries = 1024 entries per matrix per chunk.
    auto issue = [&](int c, int bi) {
        uint4* aS = smem4 + bi * STAGE_U4;
        uint4* bS = aS + 128 * PE2;
        #pragma unroll
        for (int j = tid; j < 1024; j += 256) {
            int row = j >> 3, el = j & 7;
            cp16b(aS + row * PE2 + el, &g_xpack[(size_t)(bm + row) * 64 + c * 8 + el]);
            cp16b(bS + row * PE2 + el, &g_wpack[(size_t)(bn + row) * 64 + c * 8 + el]);
        }
        asm volatile("cp.async.commit_group;");
    };

    issue(0, 0);
    for (int c = 0; c < 8; c++) {
        if (c < 7) {
            issue(c + 1, (c + 1) & 1);
            asm volatile("cp.async.wait_group 1;");
        } else {
            asm volatile("cp.async.wait_group 0;");
        }
        __syncthreads();

        const uint4* aS = smem4 + (c & 1) * STAGE_U4;
        const uint4* bS = aS + 128 * PE2;
        #pragma unroll
        for (int ks = 0; ks < 2; ks++) {
            uint4 a0r0 = aS[(wm * 32 + g) * PE2 + ks * 4 + t];
            uint4 a0r8 = aS[(wm * 32 + g + 8) * PE2 + ks * 4 + t];
            uint4 a1r0 = aS[(wm * 32 + 16 + g) * PE2 + ks * 4 + t];
            uint4 a1r8 = aS[(wm * 32 + 24 + g) * PE2 + ks * 4 + t];
            #pragma unroll
            for (int nt = 0; nt < 8; nt++) {
                uint4 b = bS[(wn * 64 + nt * 8 + g) * PE2 + ks * 4 + t];
                mma_bf16(d[0][nt], a0r0.x, a0r8.x, a0r0.y, a0r8.y, b.x, b.y);
                mma_bf16(d[0][nt], a0r0.x, a0r8.x, a0r0.y, a0r8.y, b.z, b.w);
                mma_bf16(d[0][nt], a0r0.z, a0r8.z, a0r0.w, a0r8.w, b.x, b.y);
                mma_bf16(d[1][nt], a1r0.x, a1r8.x, a1r0.y, a1r8.y, b.x, b.y);
                mma_bf16(d[1][nt], a1r0.x, a1r8.x, a1r0.y, a1r8.y, b.z, b.w);
                mma_bf16(d[1][nt], a1r0.z, a1r8.z, a1r0.w, a1r8.w, b.x, b.y);
            }
        }
        __syncthreads();   // compute(c) reads done before issue(c+2) overwrites
    }

    #pragma unroll
    for (int nt = 0; nt < 8; nt++) {
        int c0 = bn + wn * 64 + nt * 8 + 2 * t;
        float bb0 = bias[c0], bb1 = bias[c0 + 1];
        #pragma unroll
        for (int mt = 0; mt < 2; mt++) {
            int r0 = bm + wm * 32 + mt * 16 + g;
            int r1 = r0 + 8;
            size_t a0 = ((size_t)(r0 >> 6) * NG + c0) * NB + (r0 & 63);
            size_t a1 = ((size_t)(r1 >> 6) * NG + c0) * NB + (r1 & 63);
            g_xw[a0]      = d[mt][nt][0] + bb0;
            g_xw[a0 + NB] = d[mt][nt][1] + bb1;
            g_xw[a1]      = d[mt][nt][2] + bb0;
            g_xw[a1 + NB] = d[mt][nt][3] + bb1;
        }
    }
}

// ---------------- Phase 2: persistent recurrence (R14 EXACT) ----------------
#define SMEM2_FLOATS (NH * 64 + NH * 16 + 16 * 1024)

__device__ __forceinline__ unsigned long long fma2(unsigned long long a,
                                                   unsigned long long b,
                                                   unsigned long long c) {
    unsigned long long d;
    asm("fma.rn.f32x2 %0, %1, %2, %3;" : "=l"(d) : "l"(a), "l"(b), "l"(c));
    return d;
}
__device__ __forceinline__ unsigned long long pack2(float x, float y) {
    unsigned long long r;
    asm("mov.b64 %0, {%1, %2};" : "=l"(r) : "f"(x), "f"(y));
    return r;
}
__device__ __forceinline__ float2 unpack2(unsigned long long v) {
    float2 f;
    asm("mov.b64 {%0, %1}, %2;" : "=f"(f.x), "=f"(f.y) : "l"(v));
    return f;
}

__global__ void __launch_bounds__(512, 1)
lstm_rec_kernel(const float* __restrict__ Wh, float* __restrict__ out, int write_state) {
    extern __shared__ float smem[];
    float* sWh  = smem;                 // [k][64], c = gt*16+u16
    float* shT  = sWh + NH * 64;        // [k][16 batches]; first 1024 floats alias sAux
    float* sRed = shT + NH * 16;        // [w][g][b16][u16]
    float* sAux = shT;                  // [g][b16][u16] upper-half sums (4KB alias)

    const int tid = threadIdx.x;
    const int wid = tid >> 5;
    const int lane = tid & 31;
    const int ug = blockIdx.x >> 2;
    const int bgp = blockIdx.x & 3;

    for (int idx = tid; idx < NH * 64; idx += 512) {
        int k = idx >> 6, c = idx & 63;
        int gcol = ((c >> 4) << 9) + (ug << 4) + (c & 15);
        sWh[idx] = Wh[(size_t)k * NG + gcol];
    }
    __syncthreads();

    const int cg = lane >> 2, bq = lane & 3;
    const int g_of = cg >> 1, u8 = (cg & 1) << 3;
    const int srow = lane >> 2, spart = lane & 3;

    const unsigned* fl0 = &g_flag[(bgp * 32 + 2 * wid) * 32];
    const unsigned* fl1 = &g_flag[(bgp * 32 + 2 * wid + 1) * 32];
    unsigned* flown = &g_flag[(bgp * 32 + ug) * 32];

    const float* wbase = sWh + (wid << 5) * 64 + (cg << 3);
    const float* hbase = shT + (wid << 5) * 16 + (bq << 2);

    const int u_ = tid & 15, b2 = (tid >> 4) & 15;
    const int hrow = (ug << 4) + u_;
    const int bglob = (bgp << 4) + b2;
    float c_reg = 0.f;

    for (int t = 0; t < NT; t++) {
        const unsigned need = 8u * (unsigned)t;

        float xw0 = 0.f, xw1 = 0.f, xw2 = 0.f, xw3 = 0.f;
        if (tid < 256) {
            const float* xwt = g_xw + (size_t)t * ((size_t)NG * NB) + (size_t)hrow * NB + bglob;
            xw0 = __ldcs(xwt);
            xw1 = __ldcs(xwt + (size_t)(1 << 9) * NB);
            xw2 = __ldcs(xwt + (size_t)(2 << 9) * NB);
            xw3 = __ldcs(xwt + (size_t)(3 << 9) * NB);
        }

        const float* src = g_h + (t & 1) * (NH * NB) + (bgp << 4) + (spart << 2);
        unsigned long long acc[4][4];
        #pragma unroll
        for (int cp = 0; cp < 4; cp++)
            #pragma unroll
            for (int j = 0; j < 4; j++) acc[cp][j] = 0ull;

        #pragma unroll
        for (int ch = 0; ch < 2; ch++) {
            const unsigned* fl = ch ? fl1 : fl0;
            while (ld_acquire(fl) < need) { }

            const int rbase = (wid << 5) + (ch << 4);
            {
                int r0 = rbase + srow, r1 = rbase + 8 + srow;
                float4 v0 = __ldcg(reinterpret_cast<const float4*>(src + r0 * NB));
                float4 v1 = __ldcg(reinterpret_cast<const float4*>(src + r1 * NB));
                *reinterpret_cast<float4*>(shT + r0 * 16 + (spart << 2)) = v0;
                *reinterpret_cast<float4*>(shT + r1 * 16 + (spart << 2)) = v1;
            }
            __syncwarp();

            const float* wp_ = wbase + (ch << 4) * 64;
            const float* hp_ = hbase + (ch << 4) * 16;
            #pragma unroll 8
            for (int kl = 0; kl < 16; kl++) {
                ulonglong2 wA = *reinterpret_cast<const ulonglong2*>(wp_);
                ulonglong2 wB = *reinterpret_cast<const ulonglong2*>(wp_ + 4);
                float4 h = *reinterpret_cast<const float4*>(hp_);
                unsigned long long wq[4] = {wA.x, wA.y, wB.x, wB.y};
                unsigned long long hd[4] = {pack2(h.x, h.x), pack2(h.y, h.y),
                                            pack2(h.z, h.z), pack2(h.w, h.w)};
                #pragma unroll
                for (int cp = 0; cp < 4; cp++) {
                    acc[cp][0] = fma2(wq[cp], hd[0], acc[cp][0]);
                    acc[cp][1] = fma2(wq[cp], hd[1], acc[cp][1]);
                    acc[cp][2] = fma2(wq[cp], hd[2], acc[cp][2]);
                    acc[cp][3] = fma2(wq[cp], hd[3], acc[cp][3]);
                }
                wp_ += 64;
                hp_ += 16;
            }
        }

        #pragma unroll
        for (int j = 0; j < 4; j++) {
            float2 p0 = unpack2(acc[0][j]);
            float2 p1 = unpack2(acc[1][j]);
            float2 p2 = unpack2(acc[2][j]);
            float2 p3 = unpack2(acc[3][j]);
            float* dst = sRed + (wid << 10) + (g_of << 8) + (((bq << 2) + j) << 4) + u8;
            *reinterpret_cast<float4*>(dst)     = make_float4(p0.x, p0.y, p1.x, p1.y);
            *reinterpret_cast<float4*>(dst + 4) = make_float4(p2.x, p2.y, p3.x, p3.y);
        }
        __syncthreads();

        float G0, G1, G2, G3;
        if (tid >= 256) {
            float H0 = 0.f, H1 = 0.f, H2 = 0.f, H3 = 0.f;
            const float* rp = sRed + (8 << 10) + (((tid & 255) >> 4) << 4) + (tid & 15);
            #pragma unroll
            for (int w = 0; w < 8; w++) {
                H0 += rp[0];
                H1 += rp[256];
                H2 += rp[512];
                H3 += rp[768];
                rp += 1024;
            }
            float* ax = sAux + (((tid & 255) >> 4) << 4) + (tid & 15);
            ax[0] = H0;
            ax[256] = H1;
            ax[512] = H2;
            ax[768] = H3;
            G0 = G1 = G2 = G3 = 0.f;
        } else {
            G0 = xw0; G1 = xw1; G2 = xw2; G3 = xw3;
            const float* rp = sRed + (b2 << 4) + u_;
            #pragma unroll
            for (int w = 0; w < 8; w++) {
                G0 += rp[0];
                G1 += rp[256];
                G2 += rp[512];
                G3 += rp[768];
                rp += 1024;
            }
        }
        __syncthreads();

        if (tid < 256) {
            const float* ax = sAux + (b2 << 4) + u_;
            G0 += ax[0];
            G1 += ax[256];
            G2 += ax[512];
            G3 += ax[768];
            float ig = fast_sigmoid(G0);
            float fg = fast_sigmoid(G1);
            float gg = fast_tanh(G2);
            float og = fast_sigmoid(G3);
            c_reg = fg * c_reg + ig * gg;
            float h = og * fast_tanh(c_reg);

            __stcg(&g_h[((t + 1) & 1) * (NH * NB) + hrow * NB + bglob], h);
            __syncwarp();
            if ((tid & 31) == 0) {
                asm volatile("red.release.gpu.global.add.u32 [%0], %1;"
                             :: "l"(flown), "r"(1u) : "memory");
            }
            __stcs(&out[((size_t)t * NB + bglob) * NH + hrow], h);
            if (write_state && t == NT - 1) {
                size_t base = (size_t)NT * NB * NH;
                out[base + (size_t)bglob * NH + hrow] = h;
                out[base + (size_t)NB * NH + (size_t)bglob * NH + hrow] = c_reg;
            }
        }
        __syncthreads();
    }
}

extern "C" void kernel_launch(void* const* d_in, const int* in_sizes, int n_in,
                              void* d_out, int out_size) {
    const float* x  = (const float*)d_in[0];
    const float* Wi = (const float*)d_in[1];
    const float* Wh = (const float*)d_in[2];
    const float* B  = (const float*)d_in[3];
    float* out = (float*)d_out;

    cudaFuncSetAttribute(xw_mma_kernel, cudaFuncAttributeMaxDynamicSharedMemorySize,
                         GEMM_SMEM);
    const int smem2 = SMEM2_FLOATS * (int)sizeof(float);   // 229376 B
    cudaFuncSetAttribute(lstm_rec_kernel, cudaFuncAttributeMaxDynamicSharedMemorySize, smem2);

    // Phase 0: pack x + Wi; init h0/flags.
    pack_kernel<<<(NT * NB * 64) / 256, 256>>>(x, Wi);

    // Phase 1: tensor-core GEMM (double-buffered K=32 chunks, occ 2).
    dim3 gA(NG / 128, (NT * NB) / 128);
    xw_mma_kernel<<<gA, 256, GEMM_SMEM>>>(B);

    const long long need_full = (long long)NT * NB * NH + 2LL * NB * NH;
    int write_state = ((long long)out_size >= need_full) ? 1 : 0;

    // Phase 2: persistent recurrence (R14).
    lstm_rec_kernel<<<GRID_B, 512, smem2>>>(Wh, out, write_state);
}